// round 1
// baseline (speedup 1.0000x reference)
#include <cuda_runtime.h>
#include <math.h>

// Problem constants
#define BB 4
#define SS 1024
#define DD 1024
#define HH 4096
#define EE 8
#define TOPK 2
#define NT (BB * SS)   // 4096 tokens
#define CAP NT         // per-expert worst-case capacity

// ---------------- device scratch (no allocations allowed) ----------------
__device__ int   g_counts[EE];
__device__ int   g_tokens[EE * CAP];   // token index per expert slot
__device__ float g_wts[EE * CAP];      // combine weight per expert slot
__device__ float g_probsum[EE];        // sum of softmax probs per expert
// h activations, padded per expert: [E][CAP][H]  (8*4096*4096*4B = 512 MiB)
__device__ float g_h[(size_t)EE * CAP * HH];

// ---------------- init: zero routing state ----------------
__global__ void k_init() {
    int t = threadIdx.x;
    if (t < EE) { g_counts[t] = 0; g_probsum[t] = 0.0f; }
}

// ---------------- zero the output accumulator ----------------
__global__ void k_zero_out(float* __restrict__ out, int n) {
    int i = blockIdx.x * blockDim.x + threadIdx.x;
    int stride = gridDim.x * blockDim.x;
    for (; i < n; i += stride) out[i] = 0.0f;
}

// ---------------- router: logits, softmax, top-2, gather lists ----------------
// One warp per token.
__global__ void k_router(const float* __restrict__ x,
                         const float* __restrict__ rw) {
    int gwarp = (blockIdx.x * blockDim.x + threadIdx.x) >> 5;
    int lane  = threadIdx.x & 31;

    __shared__ float s_ps[EE];
    if (threadIdx.x < EE) s_ps[threadIdx.x] = 0.0f;
    __syncthreads();

    if (gwarp < NT) {
        const float* xr = x + (size_t)gwarp * DD;
        float acc[EE];
        #pragma unroll
        for (int e = 0; e < EE; e++) acc[e] = 0.0f;

        for (int k = lane; k < DD; k += 32) {
            float xv = xr[k];
            const float* r = rw + k * EE;
            #pragma unroll
            for (int e = 0; e < EE; e++) acc[e] += xv * r[e];
        }
        #pragma unroll
        for (int off = 16; off > 0; off >>= 1) {
            #pragma unroll
            for (int e = 0; e < EE; e++)
                acc[e] += __shfl_down_sync(0xffffffffu, acc[e], off);
        }

        if (lane == 0) {
            // softmax over 8 logits
            float m = acc[0];
            #pragma unroll
            for (int e = 1; e < EE; e++) m = fmaxf(m, acc[e]);
            float p[EE]; float Z = 0.0f;
            #pragma unroll
            for (int e = 0; e < EE; e++) { p[e] = expf(acc[e] - m); Z += p[e]; }
            float invZ = 1.0f / Z;
            #pragma unroll
            for (int e = 0; e < EE; e++) p[e] *= invZ;

            // top-2 (lowest index wins ties, matching lax.top_k)
            int i1 = 0;
            #pragma unroll
            for (int e = 1; e < EE; e++) if (p[e] > p[i1]) i1 = e;
            int i2 = (i1 == 0) ? 1 : 0;
            #pragma unroll
            for (int e = 0; e < EE; e++) if (e != i1 && p[e] > p[i2]) i2 = e;

            float s  = p[i1] + p[i2] + 1e-8f;
            float w1 = p[i1] / s;
            float w2 = p[i2] / s;

            int pos1 = atomicAdd(&g_counts[i1], 1);
            g_tokens[i1 * CAP + pos1] = gwarp;
            g_wts[i1 * CAP + pos1]    = w1;
            int pos2 = atomicAdd(&g_counts[i2], 1);
            g_tokens[i2 * CAP + pos2] = gwarp;
            g_wts[i2 * CAP + pos2]    = w2;

            #pragma unroll
            for (int e = 0; e < EE; e++) atomicAdd(&s_ps[e], p[e]);
        }
    }
    __syncthreads();
    if (threadIdx.x < EE) atomicAdd(&g_probsum[threadIdx.x], s_ps[threadIdx.x]);
}

// ---------------- aux loss ----------------
__global__ void k_aux(float* __restrict__ out, int out_size) {
    if (threadIdx.x == 0 && out_size > NT * DD) {
        float aux = 0.0f;
        for (int e = 0; e < EE; e++) {
            float avg_p = g_probsum[e] / (float)NT;
            float usage = (float)g_counts[e] / (float)(NT * TOPK);
            aux += avg_p * usage;
        }
        out[NT * DD] = (float)EE * aux;
    }
}

// ---------------- tiled SGEMM config ----------------
#define BM 128
#define BN 128
#define BK 8

// GEMM1: h[e, m, :] = GELU( x[token] @ W_in[e] + b_in[e] )
// grid: (HH/BN, CAP/BM, EE), block 256
__global__ __launch_bounds__(256)
void k_gemm1(const float* __restrict__ x,
             const float* __restrict__ Win,
             const float* __restrict__ bin) {
    int e  = blockIdx.z;
    int ne = g_counts[e];
    int m0 = blockIdx.y * BM;
    if (m0 >= ne) return;

    __shared__ __align__(16) float As[BK][BM];
    __shared__ __align__(16) float Bs[BK][BN];

    int tid = threadIdx.x;
    int a_m = tid >> 1;            // 0..127
    int a_k = (tid & 1) * 4;       // 0 or 4
    int b_row = tid >> 5;          // 0..7
    int b_col = (tid & 31) * 4;    // 0..124

    const float* arow = nullptr;
    if (m0 + a_m < ne) {
        int tok = g_tokens[e * CAP + m0 + a_m];
        arow = x + (size_t)tok * DD;
    }
    const float* bbase = Win + (size_t)e * DD * HH + (size_t)blockIdx.x * BN;

    float acc[8][8];
    #pragma unroll
    for (int i = 0; i < 8; i++)
        #pragma unroll
        for (int j = 0; j < 8; j++) acc[i][j] = 0.0f;

    int tx = tid & 15, ty = tid >> 4;

    for (int k0 = 0; k0 < DD; k0 += BK) {
        float4 av = make_float4(0.f, 0.f, 0.f, 0.f);
        if (arow) av = *(const float4*)(arow + k0 + a_k);
        As[a_k + 0][a_m] = av.x;
        As[a_k + 1][a_m] = av.y;
        As[a_k + 2][a_m] = av.z;
        As[a_k + 3][a_m] = av.w;
        float4 bv = *(const float4*)(bbase + (size_t)(k0 + b_row) * HH + b_col);
        *(float4*)&Bs[b_row][b_col] = bv;
        __syncthreads();

        #pragma unroll
        for (int kk = 0; kk < BK; kk++) {
            float a[8], b[8];
            *(float4*)(a)     = *(const float4*)&As[kk][ty * 8];
            *(float4*)(a + 4) = *(const float4*)&As[kk][ty * 8 + 4];
            *(float4*)(b)     = *(const float4*)&Bs[kk][tx * 8];
            *(float4*)(b + 4) = *(const float4*)&Bs[kk][tx * 8 + 4];
            #pragma unroll
            for (int i = 0; i < 8; i++)
                #pragma unroll
                for (int j = 0; j < 8; j++)
                    acc[i][j] += a[i] * b[j];
        }
        __syncthreads();
    }

    // epilogue: +bias, exact GELU, store to g_h
    int ncol0 = blockIdx.x * BN + tx * 8;
    float bi[8];
    #pragma unroll
    for (int j = 0; j < 8; j++) bi[j] = bin[e * HH + ncol0 + j];

    #pragma unroll
    for (int i = 0; i < 8; i++) {
        int m = m0 + ty * 8 + i;
        if (m < ne) {
            float* hrow = g_h + ((size_t)e * CAP + m) * HH + ncol0;
            float vout[8];
            #pragma unroll
            for (int j = 0; j < 8; j++) {
                float v = acc[i][j] + bi[j];
                vout[j] = 0.5f * v * (1.0f + erff(v * 0.70710678118654752f));
            }
            *(float4*)(hrow)     = *(float4*)(vout);
            *(float4*)(hrow + 4) = *(float4*)(vout + 4);
        }
    }
}

// GEMM2: y = h @ W_out[e] + b_out[e]; out[token] += w * y (atomic)
// grid: (DD/BN, CAP/BM, EE), block 256
__global__ __launch_bounds__(256)
void k_gemm2(const float* __restrict__ Wout,
             const float* __restrict__ bout,
             float* __restrict__ out) {
    int e  = blockIdx.z;
    int ne = g_counts[e];
    int m0 = blockIdx.y * BM;
    if (m0 >= ne) return;

    __shared__ __align__(16) float As[BK][BM];
    __shared__ __align__(16) float Bs[BK][BN];

    int tid = threadIdx.x;
    int a_m = tid >> 1;
    int a_k = (tid & 1) * 4;
    int b_row = tid >> 5;
    int b_col = (tid & 31) * 4;

    const float* arow = nullptr;
    if (m0 + a_m < ne)
        arow = g_h + ((size_t)e * CAP + m0 + a_m) * HH;
    const float* bbase = Wout + (size_t)e * HH * DD + (size_t)blockIdx.x * BN;

    float acc[8][8];
    #pragma unroll
    for (int i = 0; i < 8; i++)
        #pragma unroll
        for (int j = 0; j < 8; j++) acc[i][j] = 0.0f;

    int tx = tid & 15, ty = tid >> 4;

    for (int k0 = 0; k0 < HH; k0 += BK) {
        float4 av = make_float4(0.f, 0.f, 0.f, 0.f);
        if (arow) av = *(const float4*)(arow + k0 + a_k);
        As[a_k + 0][a_m] = av.x;
        As[a_k + 1][a_m] = av.y;
        As[a_k + 2][a_m] = av.z;
        As[a_k + 3][a_m] = av.w;
        float4 bv = *(const float4*)(bbase + (size_t)(k0 + b_row) * DD + b_col);
        *(float4*)&Bs[b_row][b_col] = bv;
        __syncthreads();

        #pragma unroll
        for (int kk = 0; kk < BK; kk++) {
            float a[8], b[8];
            *(float4*)(a)     = *(const float4*)&As[kk][ty * 8];
            *(float4*)(a + 4) = *(const float4*)&As[kk][ty * 8 + 4];
            *(float4*)(b)     = *(const float4*)&Bs[kk][tx * 8];
            *(float4*)(b + 4) = *(const float4*)&Bs[kk][tx * 8 + 4];
            #pragma unroll
            for (int i = 0; i < 8; i++)
                #pragma unroll
                for (int j = 0; j < 8; j++)
                    acc[i][j] += a[i] * b[j];
        }
        __syncthreads();
    }

    int ncol0 = blockIdx.x * BN + tx * 8;
    float bo[8];
    #pragma unroll
    for (int j = 0; j < 8; j++) bo[j] = bout[e * DD + ncol0 + j];

    #pragma unroll
    for (int i = 0; i < 8; i++) {
        int m = m0 + ty * 8 + i;
        if (m < ne) {
            int   tok = g_tokens[e * CAP + m];
            float w   = g_wts[e * CAP + m];
            float* orow = out + (size_t)tok * DD + ncol0;
            #pragma unroll
            for (int j = 0; j < 8; j++) {
                float v = acc[i][j] + bo[j];
                atomicAdd(&orow[j], w * v);
            }
        }
    }
}

// ---------------- launch ----------------
extern "C" void kernel_launch(void* const* d_in, const int* in_sizes, int n_in,
                              void* d_out, int out_size) {
    const float* x    = (const float*)d_in[0];
    const float* rw   = (const float*)d_in[1];
    const float* Win  = (const float*)d_in[2];
    const float* bin  = (const float*)d_in[3];
    const float* Wout = (const float*)d_in[4];
    const float* bout = (const float*)d_in[5];
    float* out = (float*)d_out;

    k_init<<<1, 32>>>();
    k_zero_out<<<512, 256>>>(out, NT * DD);
    k_router<<<NT / 8, 256>>>(x, rw);
    k_aux<<<1, 32>>>(out, out_size);

    dim3 g1(HH / BN, CAP / BM, EE);
    k_gemm1<<<g1, 256>>>(x, Win, bin);

    dim3 g2(DD / BN, CAP / BM, EE);
    k_gemm2<<<g2, 256>>>(Wout, bout, out);
}

// round 5
// speedup vs baseline: 5.8023x; 5.8023x over previous
#include <cuda_runtime.h>
#include <cuda_fp16.h>
#include <math.h>
#include <stdint.h>

// ---------------- problem constants ----------------
#define DDIM 1024
#define HDIM 4096
#define NEXP 8
#define NTOK 4096
#define CAPE 4096

// ---------------- tiling ----------------
#define KSTAGE 32
#define A_LD 40                       // 32 halves + 8 skew
#define B_LD 136                      // 128 halves + 8 skew
#define A_BYTES (128 * A_LD * 2)      // 10240
#define B_BYTES (KSTAGE * B_LD * 2)   // 8704
#define STAGE_BYTES (A_BYTES + B_BYTES)  // 18944
#define SMEM_TOT (2 * STAGE_BYTES)       // 37888 < 48K static

// ---------------- device scratch ----------------
__device__ int    g_counts[NEXP];
__device__ int    g_tokens[NEXP * CAPE];
__device__ float  g_wts[NEXP * CAPE];
__device__ int    g_slot[NTOK * 2];
__device__ float  g_probsum[NEXP];
__device__ __half g_x16[(size_t)NTOK * DDIM];
__device__ __half g_w1[(size_t)NEXP * DDIM * HDIM];
__device__ __half g_w2[(size_t)NEXP * HDIM * DDIM];
__device__ __half g_h16[(size_t)NEXP * CAPE * HDIM];
__device__ float  g_y[(size_t)NEXP * CAPE * DDIM];

// ---------------- helpers ----------------
__device__ __forceinline__ uint32_t smem_u32(const void* p) {
    uint32_t a;
    asm("{ .reg .u64 t; cvta.to.shared.u64 t, %1; cvt.u32.u64 %0, t; }" : "=r"(a) : "l"(p));
    return a;
}
__device__ __forceinline__ void cp16(uint32_t s, const void* g) {
    asm volatile("cp.async.cg.shared.global [%0], [%1], 16;\n" :: "r"(s), "l"(g) : "memory");
}
__device__ __forceinline__ void cp_commit() {
    asm volatile("cp.async.commit_group;\n" ::: "memory");
}
__device__ __forceinline__ void cp_wait1() {
    asm volatile("cp.async.wait_group 1;\n" ::: "memory");
}
__device__ __forceinline__ void cp_wait0() {
    asm volatile("cp.async.wait_group 0;\n" ::: "memory");
}
__device__ __forceinline__ void ldsm4(uint32_t& r0, uint32_t& r1, uint32_t& r2, uint32_t& r3, uint32_t a) {
    asm volatile("ldmatrix.sync.aligned.m8n8.x4.shared.b16 {%0,%1,%2,%3}, [%4];"
                 : "=r"(r0), "=r"(r1), "=r"(r2), "=r"(r3) : "r"(a));
}
__device__ __forceinline__ void ldsm4t(uint32_t& r0, uint32_t& r1, uint32_t& r2, uint32_t& r3, uint32_t a) {
    asm volatile("ldmatrix.sync.aligned.m8n8.x4.trans.shared.b16 {%0,%1,%2,%3}, [%4];"
                 : "=r"(r0), "=r"(r1), "=r"(r2), "=r"(r3) : "r"(a));
}
__device__ __forceinline__ void mma16816(float* c, const uint32_t* a, const uint32_t* b) {
    asm volatile(
        "mma.sync.aligned.m16n8k16.row.col.f32.f16.f16.f32 "
        "{%0,%1,%2,%3}, {%4,%5,%6,%7}, {%8,%9}, {%0,%1,%2,%3};"
        : "+f"(c[0]), "+f"(c[1]), "+f"(c[2]), "+f"(c[3])
        : "r"(a[0]), "r"(a[1]), "r"(a[2]), "r"(a[3]), "r"(b[0]), "r"(b[1]));
}

// ---------------- small kernels ----------------
__global__ void k_init() {
    int t = threadIdx.x;
    if (t < NEXP) { g_counts[t] = 0; g_probsum[t] = 0.0f; }
}

__global__ void k_router(const float* __restrict__ x, const float* __restrict__ rw) {
    int gwarp = (blockIdx.x * blockDim.x + threadIdx.x) >> 5;
    int lane  = threadIdx.x & 31;
    __shared__ float s_ps[NEXP];
    if (threadIdx.x < NEXP) s_ps[threadIdx.x] = 0.0f;
    __syncthreads();

    if (gwarp < NTOK) {
        const float* xr = x + (size_t)gwarp * DDIM;
        float acc[NEXP];
        #pragma unroll
        for (int e = 0; e < NEXP; e++) acc[e] = 0.0f;
        for (int k = lane; k < DDIM; k += 32) {
            float xv = xr[k];
            const float* r = rw + k * NEXP;
            #pragma unroll
            for (int e = 0; e < NEXP; e++) acc[e] += xv * r[e];
        }
        #pragma unroll
        for (int off = 16; off > 0; off >>= 1)
            #pragma unroll
            for (int e = 0; e < NEXP; e++)
                acc[e] += __shfl_down_sync(0xffffffffu, acc[e], off);

        if (lane == 0) {
            float m = acc[0];
            #pragma unroll
            for (int e = 1; e < NEXP; e++) m = fmaxf(m, acc[e]);
            float p[NEXP]; float Z = 0.0f;
            #pragma unroll
            for (int e = 0; e < NEXP; e++) { p[e] = expf(acc[e] - m); Z += p[e]; }
            float invZ = 1.0f / Z;
            #pragma unroll
            for (int e = 0; e < NEXP; e++) p[e] *= invZ;

            int i1 = 0;
            #pragma unroll
            for (int e = 1; e < NEXP; e++) if (p[e] > p[i1]) i1 = e;
            int i2 = (i1 == 0) ? 1 : 0;
            #pragma unroll
            for (int e = 0; e < NEXP; e++) if (e != i1 && p[e] > p[i2]) i2 = e;

            float s  = p[i1] + p[i2] + 1e-8f;
            int pos1 = atomicAdd(&g_counts[i1], 1);
            g_tokens[i1 * CAPE + pos1] = gwarp;
            g_wts[i1 * CAPE + pos1]    = p[i1] / s;
            g_slot[gwarp * 2 + 0]      = i1 * CAPE + pos1;
            int pos2 = atomicAdd(&g_counts[i2], 1);
            g_tokens[i2 * CAPE + pos2] = gwarp;
            g_wts[i2 * CAPE + pos2]    = p[i2] / s;
            g_slot[gwarp * 2 + 1]      = i2 * CAPE + pos2;

            #pragma unroll
            for (int e = 0; e < NEXP; e++) atomicAdd(&s_ps[e], p[e]);
        }
    }
    __syncthreads();
    if (threadIdx.x < NEXP) atomicAdd(&g_probsum[threadIdx.x], s_ps[threadIdx.x]);
}

__global__ void k_aux(float* __restrict__ out, int out_size) {
    if (threadIdx.x == 0 && out_size > NTOK * DDIM) {
        float aux = 0.0f;
        for (int e = 0; e < NEXP; e++) {
            float avg_p = g_probsum[e] / (float)NTOK;
            float usage = (float)g_counts[e] / (float)(NTOK * 2);
            aux += avg_p * usage;
        }
        out[NTOK * DDIM] = (float)NEXP * aux;
    }
}

// fp32 -> fp16 converts. NOTE: __device__ globals are referenced ONLY from
// device code here (passing their address from host was the R3/R4 crash).
__device__ __forceinline__ void cvt_body(const float* __restrict__ s,
                                         __half* __restrict__ d, size_t n) {
    size_t stride = (size_t)gridDim.x * blockDim.x * 4;
    for (size_t i = ((size_t)blockIdx.x * blockDim.x + threadIdx.x) * 4; i < n; i += stride) {
        float4 v = *(const float4*)(s + i);
        *(__half2*)(d + i)     = __halves2half2(__float2half_rn(v.x), __float2half_rn(v.y));
        *(__half2*)(d + i + 2) = __halves2half2(__float2half_rn(v.z), __float2half_rn(v.w));
    }
}
__global__ void k_cvt_x(const float* __restrict__ s) {
    cvt_body(s, g_x16, (size_t)NTOK * DDIM);
}
__global__ void k_cvt_w1(const float* __restrict__ s) {
    cvt_body(s, g_w1, (size_t)NEXP * DDIM * HDIM);
}
__global__ void k_cvt_w2(const float* __restrict__ s) {
    cvt_body(s, g_w2, (size_t)NEXP * HDIM * DDIM);
}

// ---------------- mainloop (2-stage cp.async, mma.sync) ----------------
// A: [rows][KTOT] row-major (optional gather), B: [KTOT][NS] row-major.
// acc[i][jn][4]: warp tile 64x32 at (wm*64, wn*32) in the 128x128 CTA tile.
template <int KTOT, int NS>
__device__ __forceinline__ void mainloop(
    const __half* __restrict__ Abase,
    const __half* __restrict__ Bn0,
    const int* __restrict__ gather,
    int m0, int ne, char* dsm,
    float (&acc)[4][4][4], int wm, int wn)
{
    const int tid = threadIdx.x;
    const int lane = tid & 31;
    uint32_t sbase = smem_u32(dsm);

    size_t aoff[2]; uint32_t adst[2];
    #pragma unroll
    for (int t = 0; t < 2; t++) {
        int c = tid + t * 256;
        int row = c >> 2, sub = c & 3;
        int m = m0 + row;
        int ridx = gather ? ((m < ne) ? gather[m] : 0) : m;
        aoff[t] = (size_t)ridx * KTOT + sub * 8;
        adst[t] = (uint32_t)(row * (A_LD * 2) + sub * 16);
    }
    size_t boff[2]; uint32_t bdst[2];
    #pragma unroll
    for (int t = 0; t < 2; t++) {
        int c = tid + t * 256;
        int row = c >> 4, sub = c & 15;
        boff[t] = (size_t)row * NS + sub * 8;
        bdst[t] = (uint32_t)(A_BYTES + row * (B_LD * 2) + sub * 16);
    }

    auto issue = [&](int ks) {
        uint32_t sb = sbase + (ks & 1) * STAGE_BYTES;
        int k0 = ks * KSTAGE;
        cp16(sb + adst[0], Abase + aoff[0] + k0);
        cp16(sb + adst[1], Abase + aoff[1] + k0);
        const __half* bk = Bn0 + (size_t)k0 * NS;
        cp16(sb + bdst[0], bk + boff[0]);
        cp16(sb + bdst[1], bk + boff[1]);
        cp_commit();
    };

    const uint32_t a_lane = (uint32_t)((lane & 15) * (A_LD * 2) + (lane >> 4) * 16);
    const uint32_t b_lane = (uint32_t)((lane & 15) * (B_LD * 2) + (lane >> 4) * 16);

    constexpr int NK = KTOT / KSTAGE;
    issue(0);

    for (int ks = 0; ks < NK; ks++) {
        if (ks + 1 < NK) { issue(ks + 1); cp_wait1(); }
        else             { cp_wait0(); }
        __syncthreads();

        uint32_t As = sbase + (ks & 1) * STAGE_BYTES;
        uint32_t Bs = As + A_BYTES;

        #pragma unroll
        for (int kk = 0; kk < 2; kk++) {
            uint32_t b[8];
            uint32_t bb = Bs + kk * 16 * (B_LD * 2) + wn * 64 + b_lane;
            ldsm4t(b[0], b[1], b[2], b[3], bb);        // cols wn*32 .. +15
            ldsm4t(b[4], b[5], b[6], b[7], bb + 32);   // cols +16 .. +31
            #pragma unroll
            for (int i = 0; i < 4; i++) {
                uint32_t a[4];
                ldsm4(a[0], a[1], a[2], a[3],
                      As + (uint32_t)((wm * 64 + i * 16) * (A_LD * 2)) + kk * 32 + a_lane);
                #pragma unroll
                for (int jn = 0; jn < 4; jn++)
                    mma16816(acc[i][jn], a, &b[jn * 2]);
            }
        }
        __syncthreads();
    }
}

// ---------------- GEMM1: h = GELU(x @ W_in + b_in) -> fp16 ----------------
__global__ __launch_bounds__(256) void k_gemm1(const float* __restrict__ bin) {
    int e  = blockIdx.z;
    int ne = g_counts[e];
    int m0 = blockIdx.y * 128;
    if (m0 >= ne) return;
    int n0 = blockIdx.x * 128;

    __shared__ __align__(32) char dsm[SMEM_TOT];
    int tid = threadIdx.x, wid = tid >> 5, lane = tid & 31;
    int wm = wid >> 2, wn = wid & 3;

    float acc[4][4][4];
    #pragma unroll
    for (int i = 0; i < 4; i++)
        #pragma unroll
        for (int j = 0; j < 4; j++)
            #pragma unroll
            for (int q = 0; q < 4; q++) acc[i][j][q] = 0.0f;

    mainloop<DDIM, HDIM>(g_x16, g_w1 + (size_t)e * DDIM * HDIM + n0,
                         g_tokens + e * CAPE, m0, ne, dsm, acc, wm, wn);

    int gid = lane >> 2, t4 = lane & 3;
    #pragma unroll
    for (int i = 0; i < 4; i++) {
        int r0 = m0 + wm * 64 + i * 16 + gid;
        int r1 = r0 + 8;
        #pragma unroll
        for (int jn = 0; jn < 4; jn++) {
            int col = n0 + wn * 32 + jn * 8 + t4 * 2;
            float b0 = bin[e * HDIM + col], b1 = bin[e * HDIM + col + 1];
            if (r0 < ne) {
                float v0 = acc[i][jn][0] + b0;
                float v1 = acc[i][jn][1] + b1;
                v0 = 0.5f * v0 * (1.0f + erff(v0 * 0.70710678118654752f));
                v1 = 0.5f * v1 * (1.0f + erff(v1 * 0.70710678118654752f));
                *(__half2*)(g_h16 + ((size_t)e * CAPE + r0) * HDIM + col) =
                    __halves2half2(__float2half_rn(v0), __float2half_rn(v1));
            }
            if (r1 < ne) {
                float v2 = acc[i][jn][2] + b0;
                float v3 = acc[i][jn][3] + b1;
                v2 = 0.5f * v2 * (1.0f + erff(v2 * 0.70710678118654752f));
                v3 = 0.5f * v3 * (1.0f + erff(v3 * 0.70710678118654752f));
                *(__half2*)(g_h16 + ((size_t)e * CAPE + r1) * HDIM + col) =
                    __halves2half2(__float2half_rn(v2), __float2half_rn(v3));
            }
        }
    }
}

// ---------------- GEMM2: y = h @ W_out + b_out -> fp32 slots ----------------
__global__ __launch_bounds__(256) void k_gemm2(const float* __restrict__ bout) {
    int e  = blockIdx.z;
    int ne = g_counts[e];
    int m0 = blockIdx.y * 128;
    if (m0 >= ne) return;
    int n0 = blockIdx.x * 128;

    __shared__ __align__(32) char dsm[SMEM_TOT];
    int tid = threadIdx.x, wid = tid >> 5, lane = tid & 31;
    int wm = wid >> 2, wn = wid & 3;

    float acc[4][4][4];
    #pragma unroll
    for (int i = 0; i < 4; i++)
        #pragma unroll
        for (int j = 0; j < 4; j++)
            #pragma unroll
            for (int q = 0; q < 4; q++) acc[i][j][q] = 0.0f;

    mainloop<HDIM, DDIM>(g_h16 + (size_t)e * CAPE * HDIM,
                         g_w2 + (size_t)e * HDIM * DDIM + n0,
                         nullptr, m0, ne, dsm, acc, wm, wn);

    int gid = lane >> 2, t4 = lane & 3;
    #pragma unroll
    for (int i = 0; i < 4; i++) {
        int r0 = m0 + wm * 64 + i * 16 + gid;
        int r1 = r0 + 8;
        #pragma unroll
        for (int jn = 0; jn < 4; jn++) {
            int col = n0 + wn * 32 + jn * 8 + t4 * 2;
            float b0 = bout[e * DDIM + col], b1 = bout[e * DDIM + col + 1];
            if (r0 < ne) {
                float2 v = make_float2(acc[i][jn][0] + b0, acc[i][jn][1] + b1);
                *(float2*)(g_y + ((size_t)e * CAPE + r0) * DDIM + col) = v;
            }
            if (r1 < ne) {
                float2 v = make_float2(acc[i][jn][2] + b0, acc[i][jn][3] + b1);
                *(float2*)(g_y + ((size_t)e * CAPE + r1) * DDIM + col) = v;
            }
        }
    }
}

// ---------------- combine ----------------
__global__ void k_combine(float* __restrict__ out) {
    int tok = blockIdx.x;
    int s1 = g_slot[tok * 2], s2 = g_slot[tok * 2 + 1];
    float w1 = g_wts[s1], w2 = g_wts[s2];
    const float4* y1 = (const float4*)(g_y + (size_t)s1 * DDIM);
    const float4* y2 = (const float4*)(g_y + (size_t)s2 * DDIM);
    float4* o = (float4*)(out + (size_t)tok * DDIM);
    for (int i = threadIdx.x; i < DDIM / 4; i += blockDim.x) {
        float4 a = y1[i], b = y2[i];
        o[i] = make_float4(w1 * a.x + w2 * b.x, w1 * a.y + w2 * b.y,
                           w1 * a.z + w2 * b.z, w1 * a.w + w2 * b.w);
    }
}

// ---------------- launch ----------------
extern "C" void kernel_launch(void* const* d_in, const int* in_sizes, int n_in,
                              void* d_out, int out_size) {
    const float* x    = (const float*)d_in[0];
    const float* rw   = (const float*)d_in[1];
    const float* Win  = (const float*)d_in[2];
    const float* bin  = (const float*)d_in[3];
    const float* Wout = (const float*)d_in[4];
    const float* bout = (const float*)d_in[5];
    float* out = (float*)d_out;

    k_init<<<1, 32>>>();
    k_router<<<NTOK / 8, 256>>>(x, rw);
    k_aux<<<1, 32>>>(out, out_size);

    k_cvt_x<<<512, 256>>>(x);
    k_cvt_w1<<<2048, 256>>>(Win);
    k_cvt_w2<<<2048, 256>>>(Wout);

    k_gemm1<<<dim3(HDIM / 128, CAPE / 128, NEXP), 256>>>(bin);
    k_gemm2<<<dim3(DDIM / 128, CAPE / 128, NEXP), 256>>>(bout);

    k_combine<<<NTOK, 256>>>(out);
}

// round 6
// speedup vs baseline: 5.8813x; 1.0136x over previous
#include <cuda_runtime.h>
#include <cuda_fp16.h>
#include <math.h>
#include <stdint.h>

// ---------------- problem constants ----------------
#define DDIM 1024
#define HDIM 4096
#define NEXP 8
#define NTOK 4096
#define CAPE 4096

// ---------------- tiling ----------------
#define KSTAGE 32
#define A_LD 40                       // 32 halves + 8 skew
#define B_LD 136                      // 128 halves + 8 skew
#define A_BYTES (128 * A_LD * 2)      // 10240
#define B_BYTES (KSTAGE * B_LD * 2)   // 8704
#define STAGE_BYTES (A_BYTES + B_BYTES)  // 18944
#define SMEM_STA (2 * STAGE_BYTES)       // 37888 (static fallback)
#define SMEM_DYN3 (3 * STAGE_BYTES)      // 56832 (dynamic, needs attr)

// ---------------- device scratch ----------------
__device__ int    g_counts[NEXP];
__device__ int    g_tokens[NEXP * CAPE];
__device__ float  g_wts[NEXP * CAPE];
__device__ float  g_probsum[NEXP];
__device__ __half g_x16[(size_t)NTOK * DDIM];
__device__ __half g_w1[(size_t)NEXP * DDIM * HDIM];
__device__ __half g_w2[(size_t)NEXP * HDIM * DDIM];
__device__ __half g_h16[(size_t)NEXP * CAPE * HDIM];

// ---------------- helpers ----------------
__device__ __forceinline__ uint32_t smem_u32(const void* p) {
    uint32_t a;
    asm("{ .reg .u64 t; cvta.to.shared.u64 t, %1; cvt.u32.u64 %0, t; }" : "=r"(a) : "l"(p));
    return a;
}
__device__ __forceinline__ void cp16(uint32_t s, const void* g) {
    asm volatile("cp.async.cg.shared.global [%0], [%1], 16;\n" :: "r"(s), "l"(g) : "memory");
}
__device__ __forceinline__ void cp_commit() {
    asm volatile("cp.async.commit_group;\n" ::: "memory");
}
template <int N>
__device__ __forceinline__ void cp_waitn() {
    asm volatile("cp.async.wait_group %0;\n" :: "n"(N) : "memory");
}
__device__ __forceinline__ void ldsm4(uint32_t& r0, uint32_t& r1, uint32_t& r2, uint32_t& r3, uint32_t a) {
    asm volatile("ldmatrix.sync.aligned.m8n8.x4.shared.b16 {%0,%1,%2,%3}, [%4];"
                 : "=r"(r0), "=r"(r1), "=r"(r2), "=r"(r3) : "r"(a));
}
__device__ __forceinline__ void ldsm4t(uint32_t& r0, uint32_t& r1, uint32_t& r2, uint32_t& r3, uint32_t a) {
    asm volatile("ldmatrix.sync.aligned.m8n8.x4.trans.shared.b16 {%0,%1,%2,%3}, [%4];"
                 : "=r"(r0), "=r"(r1), "=r"(r2), "=r"(r3) : "r"(a));
}
__device__ __forceinline__ void mma16816(float* c, const uint32_t* a, const uint32_t* b) {
    asm volatile(
        "mma.sync.aligned.m16n8k16.row.col.f32.f16.f16.f32 "
        "{%0,%1,%2,%3}, {%4,%5,%6,%7}, {%8,%9}, {%0,%1,%2,%3};"
        : "+f"(c[0]), "+f"(c[1]), "+f"(c[2]), "+f"(c[3])
        : "r"(a[0]), "r"(a[1]), "r"(a[2]), "r"(a[3]), "r"(b[0]), "r"(b[1]));
}

// ---------------- small kernels ----------------
// cvt_x also zeroes routing state (runs before k_router in stream order).
__global__ void k_cvt_x(const float* __restrict__ s) {
    if (blockIdx.x == 0 && threadIdx.x < NEXP) {
        g_counts[threadIdx.x] = 0;
        g_probsum[threadIdx.x] = 0.0f;
    }
    size_t n = (size_t)NTOK * DDIM;
    size_t stride = (size_t)gridDim.x * blockDim.x * 4;
    for (size_t i = ((size_t)blockIdx.x * blockDim.x + threadIdx.x) * 4; i < n; i += stride) {
        float4 v = *(const float4*)(s + i);
        *(__half2*)(g_x16 + i)     = __halves2half2(__float2half_rn(v.x), __float2half_rn(v.y));
        *(__half2*)(g_x16 + i + 2) = __halves2half2(__float2half_rn(v.z), __float2half_rn(v.w));
    }
}
__device__ __forceinline__ void cvt_body(const float* __restrict__ s,
                                         __half* __restrict__ d, size_t n) {
    size_t stride = (size_t)gridDim.x * blockDim.x * 4;
    for (size_t i = ((size_t)blockIdx.x * blockDim.x + threadIdx.x) * 4; i < n; i += stride) {
        float4 v = *(const float4*)(s + i);
        *(__half2*)(d + i)     = __halves2half2(__float2half_rn(v.x), __float2half_rn(v.y));
        *(__half2*)(d + i + 2) = __halves2half2(__float2half_rn(v.z), __float2half_rn(v.w));
    }
}
__global__ void k_cvt_w1(const float* __restrict__ s) {
    cvt_body(s, g_w1, (size_t)NEXP * DDIM * HDIM);
}
__global__ void k_cvt_w2(const float* __restrict__ s) {
    cvt_body(s, g_w2, (size_t)NEXP * HDIM * DDIM);
}

__global__ void k_router(const float* __restrict__ x, const float* __restrict__ rw) {
    int gwarp = (blockIdx.x * blockDim.x + threadIdx.x) >> 5;
    int lane  = threadIdx.x & 31;
    __shared__ float s_ps[NEXP];
    if (threadIdx.x < NEXP) s_ps[threadIdx.x] = 0.0f;
    __syncthreads();

    if (gwarp < NTOK) {
        const float* xr = x + (size_t)gwarp * DDIM;
        float acc[NEXP];
        #pragma unroll
        for (int e = 0; e < NEXP; e++) acc[e] = 0.0f;
        for (int k = lane; k < DDIM; k += 32) {
            float xv = xr[k];
            const float* r = rw + k * NEXP;
            #pragma unroll
            for (int e = 0; e < NEXP; e++) acc[e] += xv * r[e];
        }
        #pragma unroll
        for (int off = 16; off > 0; off >>= 1)
            #pragma unroll
            for (int e = 0; e < NEXP; e++)
                acc[e] += __shfl_down_sync(0xffffffffu, acc[e], off);

        if (lane == 0) {
            float m = acc[0];
            #pragma unroll
            for (int e = 1; e < NEXP; e++) m = fmaxf(m, acc[e]);
            float p[NEXP]; float Z = 0.0f;
            #pragma unroll
            for (int e = 0; e < NEXP; e++) { p[e] = expf(acc[e] - m); Z += p[e]; }
            float invZ = 1.0f / Z;
            #pragma unroll
            for (int e = 0; e < NEXP; e++) p[e] *= invZ;

            int i1 = 0;
            #pragma unroll
            for (int e = 1; e < NEXP; e++) if (p[e] > p[i1]) i1 = e;
            int i2 = (i1 == 0) ? 1 : 0;
            #pragma unroll
            for (int e = 0; e < NEXP; e++) if (e != i1 && p[e] > p[i2]) i2 = e;

            float s  = p[i1] + p[i2] + 1e-8f;
            int pos1 = atomicAdd(&g_counts[i1], 1);
            g_tokens[i1 * CAPE + pos1] = gwarp;
            g_wts[i1 * CAPE + pos1]    = p[i1] / s;
            int pos2 = atomicAdd(&g_counts[i2], 1);
            g_tokens[i2 * CAPE + pos2] = gwarp;
            g_wts[i2 * CAPE + pos2]    = p[i2] / s;

            #pragma unroll
            for (int e = 0; e < NEXP; e++) atomicAdd(&s_ps[e], p[e]);
        }
    }
    __syncthreads();
    if (threadIdx.x < NEXP) atomicAdd(&g_probsum[threadIdx.x], s_ps[threadIdx.x]);
}

__global__ void k_aux(float* __restrict__ out, int out_size) {
    if (threadIdx.x == 0 && out_size > NTOK * DDIM) {
        float aux = 0.0f;
        for (int e = 0; e < NEXP; e++) {
            float avg_p = g_probsum[e] / (float)NTOK;
            float usage = (float)g_counts[e] / (float)(NTOK * 2);
            aux += avg_p * usage;
        }
        out[NTOK * DDIM] = (float)NEXP * aux;
    }
}

__global__ void k_zero_out(float* __restrict__ out) {
    size_t n = (size_t)NTOK * DDIM;
    size_t stride = (size_t)gridDim.x * blockDim.x;
    for (size_t i = (size_t)blockIdx.x * blockDim.x + threadIdx.x; i < n; i += stride)
        out[i] = 0.0f;
}

// ---------------- mainloop (multistage cp.async, single sync/iter) ----------------
template <int KTOT, int NS, int STAGES>
__device__ __forceinline__ void mainloop(
    const __half* __restrict__ Abase,
    const __half* __restrict__ Bn0,
    const int* __restrict__ gather,
    int m0, int ne, char* dsm,
    float (&acc)[4][4][4], int wm, int wn)
{
    const int tid = threadIdx.x;
    const int lane = tid & 31;
    uint32_t sbase = smem_u32(dsm);

    size_t aoff[2]; uint32_t adst[2];
    #pragma unroll
    for (int t = 0; t < 2; t++) {
        int c = tid + t * 256;
        int row = c >> 2, sub = c & 3;
        int m = m0 + row;
        int ridx = gather ? ((m < ne) ? gather[m] : 0) : m;
        aoff[t] = (size_t)ridx * KTOT + sub * 8;
        adst[t] = (uint32_t)(row * (A_LD * 2) + sub * 16);
    }
    size_t boff[2]; uint32_t bdst[2];
    #pragma unroll
    for (int t = 0; t < 2; t++) {
        int c = tid + t * 256;
        int row = c >> 4, sub = c & 15;
        boff[t] = (size_t)row * NS + sub * 8;
        bdst[t] = (uint32_t)(A_BYTES + row * (B_LD * 2) + sub * 16);
    }

    auto issue = [&](int ks) {
        uint32_t sb = sbase + (ks % STAGES) * STAGE_BYTES;
        int k0 = ks * KSTAGE;
        cp16(sb + adst[0], Abase + aoff[0] + k0);
        cp16(sb + adst[1], Abase + aoff[1] + k0);
        const __half* bk = Bn0 + (size_t)k0 * NS;
        cp16(sb + bdst[0], bk + boff[0]);
        cp16(sb + bdst[1], bk + boff[1]);
        cp_commit();
    };

    const uint32_t a_lane = (uint32_t)((lane & 15) * (A_LD * 2) + (lane >> 4) * 16);
    const uint32_t b_lane = (uint32_t)((lane & 15) * (B_LD * 2) + (lane >> 4) * 16);

    constexpr int NK = KTOT / KSTAGE;
    #pragma unroll
    for (int s = 0; s < STAGES - 1; s++) issue(s);

    for (int ks = 0; ks < NK; ks++) {
        if (ks == NK - 1) cp_waitn<0>();
        else              cp_waitn<STAGES - 2>();
        __syncthreads();
        if (ks + STAGES - 1 < NK) issue(ks + STAGES - 1);

        uint32_t As = sbase + (ks % STAGES) * STAGE_BYTES;
        uint32_t Bs = As + A_BYTES;

        #pragma unroll
        for (int kk = 0; kk < 2; kk++) {
            uint32_t b[8];
            uint32_t bb = Bs + kk * 16 * (B_LD * 2) + wn * 64 + b_lane;
            ldsm4t(b[0], b[1], b[2], b[3], bb);
            ldsm4t(b[4], b[5], b[6], b[7], bb + 32);
            #pragma unroll
            for (int i = 0; i < 4; i++) {
                uint32_t a[4];
                ldsm4(a[0], a[1], a[2], a[3],
                      As + (uint32_t)((wm * 64 + i * 16) * (A_LD * 2)) + kk * 32 + a_lane);
                #pragma unroll
                for (int jn = 0; jn < 4; jn++)
                    mma16816(acc[i][jn], a, &b[jn * 2]);
            }
        }
    }
}

// ---------------- epilogues ----------------
__device__ __forceinline__ void epi1(int e, int ne, int m0, int n0, int wm, int wn,
                                     int lane, float (&acc)[4][4][4],
                                     const float* __restrict__ bin) {
    int gid = lane >> 2, t4 = lane & 3;
    #pragma unroll
    for (int i = 0; i < 4; i++) {
        int r0 = m0 + wm * 64 + i * 16 + gid;
        int r1 = r0 + 8;
        #pragma unroll
        for (int jn = 0; jn < 4; jn++) {
            int col = n0 + wn * 32 + jn * 8 + t4 * 2;
            float b0 = bin[e * HDIM + col], b1 = bin[e * HDIM + col + 1];
            if (r0 < ne) {
                float v0 = acc[i][jn][0] + b0;
                float v1 = acc[i][jn][1] + b1;
                v0 = 0.5f * v0 * (1.0f + erff(v0 * 0.70710678118654752f));
                v1 = 0.5f * v1 * (1.0f + erff(v1 * 0.70710678118654752f));
                *(__half2*)(g_h16 + ((size_t)e * CAPE + r0) * HDIM + col) =
                    __halves2half2(__float2half_rn(v0), __float2half_rn(v1));
            }
            if (r1 < ne) {
                float v2 = acc[i][jn][2] + b0;
                float v3 = acc[i][jn][3] + b1;
                v2 = 0.5f * v2 * (1.0f + erff(v2 * 0.70710678118654752f));
                v3 = 0.5f * v3 * (1.0f + erff(v3 * 0.70710678118654752f));
                *(__half2*)(g_h16 + ((size_t)e * CAPE + r1) * HDIM + col) =
                    __halves2half2(__float2half_rn(v2), __float2half_rn(v3));
            }
        }
    }
}

__device__ __forceinline__ void epi2(int e, int ne, int m0, int n0, int wm, int wn,
                                     int lane, float (&acc)[4][4][4],
                                     const float* __restrict__ bout,
                                     float* __restrict__ out) {
    int gid = lane >> 2, t4 = lane & 3;
    #pragma unroll
    for (int i = 0; i < 4; i++) {
        int r0 = m0 + wm * 64 + i * 16 + gid;
        int r1 = r0 + 8;
        int tok0 = -1, tok1 = -1; float wt0 = 0.0f, wt1 = 0.0f;
        if (r0 < ne) { tok0 = g_tokens[e * CAPE + r0]; wt0 = g_wts[e * CAPE + r0]; }
        if (r1 < ne) { tok1 = g_tokens[e * CAPE + r1]; wt1 = g_wts[e * CAPE + r1]; }
        #pragma unroll
        for (int jn = 0; jn < 4; jn++) {
            int col = n0 + wn * 32 + jn * 8 + t4 * 2;
            float b0 = bout[e * DDIM + col], b1 = bout[e * DDIM + col + 1];
            if (tok0 >= 0) {
                atomicAdd(out + (size_t)tok0 * DDIM + col,     wt0 * (acc[i][jn][0] + b0));
                atomicAdd(out + (size_t)tok0 * DDIM + col + 1, wt0 * (acc[i][jn][1] + b1));
            }
            if (tok1 >= 0) {
                atomicAdd(out + (size_t)tok1 * DDIM + col,     wt1 * (acc[i][jn][2] + b0));
                atomicAdd(out + (size_t)tok1 * DDIM + col + 1, wt1 * (acc[i][jn][3] + b1));
            }
        }
    }
}

// ---------------- gemm bodies ----------------
template <int STAGES>
__device__ __forceinline__ void gemm1_body(const float* __restrict__ bin, char* dsm) {
    int e  = blockIdx.z;
    int ne = g_counts[e];
    int m0 = blockIdx.y * 128;
    if (m0 >= ne) return;
    int n0 = blockIdx.x * 128;
    int tid = threadIdx.x, wid = tid >> 5, lane = tid & 31;
    int wm = wid >> 2, wn = wid & 3;

    float acc[4][4][4];
    #pragma unroll
    for (int i = 0; i < 4; i++)
        #pragma unroll
        for (int j = 0; j < 4; j++)
            #pragma unroll
            for (int q = 0; q < 4; q++) acc[i][j][q] = 0.0f;

    mainloop<DDIM, HDIM, STAGES>(g_x16, g_w1 + (size_t)e * DDIM * HDIM + n0,
                                 g_tokens + e * CAPE, m0, ne, dsm, acc, wm, wn);
    epi1(e, ne, m0, n0, wm, wn, lane, acc, bin);
}

template <int STAGES>
__device__ __forceinline__ void gemm2_body(const float* __restrict__ bout,
                                           float* __restrict__ out, char* dsm) {
    int e  = blockIdx.z;
    int ne = g_counts[e];
    int m0 = blockIdx.y * 128;
    if (m0 >= ne) return;
    int n0 = blockIdx.x * 128;
    int tid = threadIdx.x, wid = tid >> 5, lane = tid & 31;
    int wm = wid >> 2, wn = wid & 3;

    float acc[4][4][4];
    #pragma unroll
    for (int i = 0; i < 4; i++)
        #pragma unroll
        for (int j = 0; j < 4; j++)
            #pragma unroll
            for (int q = 0; q < 4; q++) acc[i][j][q] = 0.0f;

    mainloop<HDIM, DDIM, STAGES>(g_h16 + (size_t)e * CAPE * HDIM,
                                 g_w2 + (size_t)e * HDIM * DDIM + n0,
                                 nullptr, m0, ne, dsm, acc, wm, wn);
    epi2(e, ne, m0, n0, wm, wn, lane, acc, bout, out);
}

// dynamic-smem (3-stage) kernels
__global__ __launch_bounds__(256) void k_gemm1_dyn(const float* __restrict__ bin) {
    extern __shared__ __align__(32) char dsm[];
    gemm1_body<3>(bin, dsm);
}
__global__ __launch_bounds__(256) void k_gemm2_dyn(const float* __restrict__ bout,
                                                   float* __restrict__ out) {
    extern __shared__ __align__(32) char dsm[];
    gemm2_body<3>(bout, out, dsm);
}
// static-smem (2-stage) fallback kernels
__global__ __launch_bounds__(256) void k_gemm1_sta(const float* __restrict__ bin) {
    __shared__ __align__(32) char dsm[SMEM_STA];
    gemm1_body<2>(bin, dsm);
}
__global__ __launch_bounds__(256) void k_gemm2_sta(const float* __restrict__ bout,
                                                   float* __restrict__ out) {
    __shared__ __align__(32) char dsm[SMEM_STA];
    gemm2_body<2>(bout, out, dsm);
}

// ---------------- launch ----------------
extern "C" void kernel_launch(void* const* d_in, const int* in_sizes, int n_in,
                              void* d_out, int out_size) {
    const float* x    = (const float*)d_in[0];
    const float* rw   = (const float*)d_in[1];
    const float* Win  = (const float*)d_in[2];
    const float* bin  = (const float*)d_in[3];
    const float* Wout = (const float*)d_in[4];
    const float* bout = (const float*)d_in[5];
    float* out = (float*)d_out;

    cudaError_t a1 = cudaFuncSetAttribute(
        k_gemm1_dyn, cudaFuncAttributeMaxDynamicSharedMemorySize, SMEM_DYN3);
    cudaError_t a2 = cudaFuncSetAttribute(
        k_gemm2_dyn, cudaFuncAttributeMaxDynamicSharedMemorySize, SMEM_DYN3);
    bool use_dyn = (a1 == cudaSuccess) && (a2 == cudaSuccess);

    dim3 g1(HDIM / 128, CAPE / 128, NEXP);
    dim3 g2(DDIM / 128, CAPE / 128, NEXP);

    k_cvt_x<<<512, 256>>>(x);                    // also zeroes routing state
    k_router<<<NTOK / 8, 256>>>(x, rw);
    k_cvt_w1<<<2048, 256>>>(Win);
    if (use_dyn) k_gemm1_dyn<<<g1, 256, SMEM_DYN3>>>(bin);
    else         k_gemm1_sta<<<g1, 256>>>(bin);
    k_cvt_w2<<<2048, 256>>>(Wout);
    k_zero_out<<<512, 256>>>(out);
    if (use_dyn) k_gemm2_dyn<<<g2, 256, SMEM_DYN3>>>(bout, out);
    else         k_gemm2_sta<<<g2, 256>>>(bout, out);
    k_aux<<<1, 32>>>(out, out_size);
}

// round 8
// speedup vs baseline: 6.2508x; 1.0628x over previous
#include <cuda_runtime.h>
#include <cuda_fp16.h>
#include <math.h>
#include <stdint.h>

// ---------------- problem constants ----------------
#define DDIM 1024
#define HDIM 4096
#define NEXP 8
#define NTOK 4096
#define CAPE 4096

// ---------------- tiling (dyn path: KSTAGE=64, 3 stages) ----------------
#define KS64 64
#define A_LD64 72                         // 64 halves + 8 skew
#define B_LD64 136                        // 128 halves + 8 skew
#define A_BYTES64 (128 * A_LD64 * 2)      // 18432
#define B_BYTES64 (KS64 * B_LD64 * 2)     // 17408
#define STAGE64 (A_BYTES64 + B_BYTES64)   // 35840
#define SMEM_DYN (3 * STAGE64)            // 107520

// ---------------- tiling (static fallback: KSTAGE=32, 2 stages) ----------------
#define KS32 32
#define A_LD32 40
#define B_LD32 136
#define A_BYTES32 (128 * A_LD32 * 2)      // 10240
#define B_BYTES32 (KS32 * B_LD32 * 2)     // 8704
#define STAGE32 (A_BYTES32 + B_BYTES32)   // 18944
#define SMEM_STA (2 * STAGE32)            // 37888

// ---------------- device scratch ----------------
__device__ int    g_counts[NEXP];
__device__ int    g_tokens[NEXP * CAPE];
__device__ float  g_wts[NEXP * CAPE];
__device__ float  g_probsum[NEXP];
__device__ __half g_x16[(size_t)NTOK * DDIM];
__device__ __half g_w1[(size_t)NEXP * DDIM * HDIM];
__device__ __half g_w2[(size_t)NEXP * HDIM * DDIM];
__device__ __half g_h16[(size_t)NEXP * CAPE * HDIM];

// ---------------- helpers ----------------
__device__ __forceinline__ uint32_t smem_u32(const void* p) {
    uint32_t a;
    asm("{ .reg .u64 t; cvta.to.shared.u64 t, %1; cvt.u32.u64 %0, t; }" : "=r"(a) : "l"(p));
    return a;
}
__device__ __forceinline__ void cp16(uint32_t s, const void* g) {
    asm volatile("cp.async.cg.shared.global [%0], [%1], 16;\n" :: "r"(s), "l"(g) : "memory");
}
__device__ __forceinline__ void cp_commit() {
    asm volatile("cp.async.commit_group;\n" ::: "memory");
}
template <int N>
__device__ __forceinline__ void cp_waitn() {
    asm volatile("cp.async.wait_group %0;\n" :: "n"(N) : "memory");
}
__device__ __forceinline__ void ldsm4(uint32_t& r0, uint32_t& r1, uint32_t& r2, uint32_t& r3, uint32_t a) {
    asm volatile("ldmatrix.sync.aligned.m8n8.x4.shared.b16 {%0,%1,%2,%3}, [%4];"
                 : "=r"(r0), "=r"(r1), "=r"(r2), "=r"(r3) : "r"(a));
}
__device__ __forceinline__ void ldsm4t(uint32_t& r0, uint32_t& r1, uint32_t& r2, uint32_t& r3, uint32_t a) {
    asm volatile("ldmatrix.sync.aligned.m8n8.x4.trans.shared.b16 {%0,%1,%2,%3}, [%4];"
                 : "=r"(r0), "=r"(r1), "=r"(r2), "=r"(r3) : "r"(a));
}
__device__ __forceinline__ void mma16816(float* c, const uint32_t* a, const uint32_t* b) {
    asm volatile(
        "mma.sync.aligned.m16n8k16.row.col.f32.f16.f16.f32 "
        "{%0,%1,%2,%3}, {%4,%5,%6,%7}, {%8,%9}, {%0,%1,%2,%3};"
        : "+f"(c[0]), "+f"(c[1]), "+f"(c[2]), "+f"(c[3])
        : "r"(a[0]), "r"(a[1]), "r"(a[2]), "r"(a[3]), "r"(b[0]), "r"(b[1]));
}

// ---------------- small kernels ----------------
__global__ void k_cvt_x(const float* __restrict__ s) {
    if (blockIdx.x == 0 && threadIdx.x < NEXP) {
        g_counts[threadIdx.x] = 0;
        g_probsum[threadIdx.x] = 0.0f;
    }
    size_t n = (size_t)NTOK * DDIM;
    size_t stride = (size_t)gridDim.x * blockDim.x * 8;
    for (size_t i = ((size_t)blockIdx.x * blockDim.x + threadIdx.x) * 8; i < n; i += stride) {
        float4 v0 = *(const float4*)(s + i);
        float4 v1 = *(const float4*)(s + i + 4);
        uint4 st;
        __half2 h;
        h = __halves2half2(__float2half_rn(v0.x), __float2half_rn(v0.y)); st.x = *(uint32_t*)&h;
        h = __halves2half2(__float2half_rn(v0.z), __float2half_rn(v0.w)); st.y = *(uint32_t*)&h;
        h = __halves2half2(__float2half_rn(v1.x), __float2half_rn(v1.y)); st.z = *(uint32_t*)&h;
        h = __halves2half2(__float2half_rn(v1.z), __float2half_rn(v1.w)); st.w = *(uint32_t*)&h;
        *(uint4*)(g_x16 + i) = st;
    }
}

__device__ __forceinline__ void cvt_body(const float* __restrict__ s,
                                         __half* __restrict__ d, size_t n) {
    size_t stride = (size_t)gridDim.x * blockDim.x * 8;
    for (size_t i = ((size_t)blockIdx.x * blockDim.x + threadIdx.x) * 8; i < n; i += stride) {
        float4 v0 = *(const float4*)(s + i);
        float4 v1 = *(const float4*)(s + i + 4);
        uint4 st;
        __half2 h;
        h = __halves2half2(__float2half_rn(v0.x), __float2half_rn(v0.y)); st.x = *(uint32_t*)&h;
        h = __halves2half2(__float2half_rn(v0.z), __float2half_rn(v0.w)); st.y = *(uint32_t*)&h;
        h = __halves2half2(__float2half_rn(v1.x), __float2half_rn(v1.y)); st.z = *(uint32_t*)&h;
        h = __halves2half2(__float2half_rn(v1.z), __float2half_rn(v1.w)); st.w = *(uint32_t*)&h;
        *(uint4*)(d + i) = st;
    }
}
__global__ void k_cvt_w1(const float* __restrict__ s) {
    cvt_body(s, g_w1, (size_t)NEXP * DDIM * HDIM);
}
__global__ void k_cvt_w2(const float* __restrict__ s) {
    cvt_body(s, g_w2, (size_t)NEXP * HDIM * DDIM);
}

__global__ void k_router(const float* __restrict__ x, const float* __restrict__ rw) {
    int gwarp = (blockIdx.x * blockDim.x + threadIdx.x) >> 5;
    int lane  = threadIdx.x & 31;
    __shared__ float s_ps[NEXP];
    if (threadIdx.x < NEXP) s_ps[threadIdx.x] = 0.0f;
    __syncthreads();

    if (gwarp < NTOK) {
        const float* xr = x + (size_t)gwarp * DDIM;
        float acc[NEXP];
        #pragma unroll
        for (int e = 0; e < NEXP; e++) acc[e] = 0.0f;
        for (int k = lane; k < DDIM; k += 32) {
            float xv = xr[k];
            const float* r = rw + k * NEXP;
            #pragma unroll
            for (int e = 0; e < NEXP; e++) acc[e] += xv * r[e];
        }
        #pragma unroll
        for (int off = 16; off > 0; off >>= 1)
            #pragma unroll
            for (int e = 0; e < NEXP; e++)
                acc[e] += __shfl_down_sync(0xffffffffu, acc[e], off);

        if (lane == 0) {
            float m = acc[0];
            #pragma unroll
            for (int e = 1; e < NEXP; e++) m = fmaxf(m, acc[e]);
            float p[NEXP]; float Z = 0.0f;
            #pragma unroll
            for (int e = 0; e < NEXP; e++) { p[e] = expf(acc[e] - m); Z += p[e]; }
            float invZ = 1.0f / Z;
            #pragma unroll
            for (int e = 0; e < NEXP; e++) p[e] *= invZ;

            int i1 = 0;
            #pragma unroll
            for (int e = 1; e < NEXP; e++) if (p[e] > p[i1]) i1 = e;
            int i2 = (i1 == 0) ? 1 : 0;
            #pragma unroll
            for (int e = 0; e < NEXP; e++) if (e != i1 && p[e] > p[i2]) i2 = e;

            float s  = p[i1] + p[i2] + 1e-8f;
            int pos1 = atomicAdd(&g_counts[i1], 1);
            g_tokens[i1 * CAPE + pos1] = gwarp;
            g_wts[i1 * CAPE + pos1]    = p[i1] / s;
            int pos2 = atomicAdd(&g_counts[i2], 1);
            g_tokens[i2 * CAPE + pos2] = gwarp;
            g_wts[i2 * CAPE + pos2]    = p[i2] / s;

            #pragma unroll
            for (int e = 0; e < NEXP; e++) atomicAdd(&s_ps[e], p[e]);
        }
    }
    __syncthreads();
    if (threadIdx.x < NEXP) atomicAdd(&g_probsum[threadIdx.x], s_ps[threadIdx.x]);
}

__global__ void k_aux(float* __restrict__ out, int out_size) {
    if (threadIdx.x == 0 && out_size > NTOK * DDIM) {
        float aux = 0.0f;
        for (int e = 0; e < NEXP; e++) {
            float avg_p = g_probsum[e] / (float)NTOK;
            float usage = (float)g_counts[e] / (float)(NTOK * 2);
            aux += avg_p * usage;
        }
        out[NTOK * DDIM] = (float)NEXP * aux;
    }
}

__global__ void k_zero_out(float* __restrict__ out) {
    size_t n = (size_t)NTOK * DDIM;
    size_t stride = (size_t)gridDim.x * blockDim.x;
    for (size_t i = (size_t)blockIdx.x * blockDim.x + threadIdx.x; i < n; i += stride)
        out[i] = 0.0f;
}

// ---------------- mainloop64: KSTAGE=64, 3 stages, 1 sync/iter ----------------
template <int KTOT, int NS>
__device__ __forceinline__ void mainloop64(
    const __half* __restrict__ Abase,
    const __half* __restrict__ Bn0,
    const int* __restrict__ gather,
    int m0, int ne, char* dsm,
    float (&acc)[4][4][4], int wm, int wn)
{
    constexpr int STAGES = 3;
    const int tid = threadIdx.x;
    const int lane = tid & 31;
    uint32_t sbase = smem_u32(dsm);

    // A: 128 rows x 128B (64 halves) = 1024 chunks -> 4/thread
    size_t aoff[4]; uint32_t adst[4];
    #pragma unroll
    for (int t = 0; t < 4; t++) {
        int c = tid + t * 256;
        int row = c >> 3, sub = c & 7;
        int m = m0 + row;
        int ridx = gather ? ((m < ne) ? gather[m] : 0) : m;
        aoff[t] = (size_t)ridx * KTOT + sub * 8;
        adst[t] = (uint32_t)(row * (A_LD64 * 2) + sub * 16);
    }
    // B: 64 rows x 256B (128 halves) = 1024 chunks -> 4/thread
    size_t boff[4]; uint32_t bdst[4];
    #pragma unroll
    for (int t = 0; t < 4; t++) {
        int c = tid + t * 256;
        int row = c >> 4, sub = c & 15;
        boff[t] = (size_t)row * NS + sub * 8;
        bdst[t] = (uint32_t)(A_BYTES64 + row * (B_LD64 * 2) + sub * 16);
    }

    auto issue = [&](int ks) {
        uint32_t sb = sbase + (ks % STAGES) * STAGE64;
        int k0 = ks * KS64;
        #pragma unroll
        for (int t = 0; t < 4; t++) cp16(sb + adst[t], Abase + aoff[t] + k0);
        const __half* bk = Bn0 + (size_t)k0 * NS;
        #pragma unroll
        for (int t = 0; t < 4; t++) cp16(sb + bdst[t], bk + boff[t]);
        cp_commit();
    };

    const uint32_t a_lane = (uint32_t)((lane & 15) * (A_LD64 * 2) + (lane >> 4) * 16);
    const uint32_t b_lane = (uint32_t)((lane & 15) * (B_LD64 * 2) + (lane >> 4) * 16);

    constexpr int NK = KTOT / KS64;
    issue(0); issue(1);

    for (int ks = 0; ks < NK; ks++) {
        if (ks == NK - 1) cp_waitn<0>();
        else              cp_waitn<1>();
        __syncthreads();
        if (ks + 2 < NK) issue(ks + 2);

        uint32_t As = sbase + (ks % STAGES) * STAGE64;
        uint32_t Bs = As + A_BYTES64;

        #pragma unroll
        for (int kk = 0; kk < 4; kk++) {
            uint32_t b[8];
            uint32_t bb = Bs + kk * 16 * (B_LD64 * 2) + wn * 64 + b_lane;
            ldsm4t(b[0], b[1], b[2], b[3], bb);
            ldsm4t(b[4], b[5], b[6], b[7], bb + 32);
            #pragma unroll
            for (int i = 0; i < 4; i++) {
                uint32_t a[4];
                ldsm4(a[0], a[1], a[2], a[3],
                      As + (uint32_t)((wm * 64 + i * 16) * (A_LD64 * 2)) + kk * 32 + a_lane);
                #pragma unroll
                for (int jn = 0; jn < 4; jn++)
                    mma16816(acc[i][jn], a, &b[jn * 2]);
            }
        }
    }
}

// ---------------- mainloop32 (static fallback, 2-stage) ----------------
template <int KTOT, int NS>
__device__ __forceinline__ void mainloop32(
    const __half* __restrict__ Abase,
    const __half* __restrict__ Bn0,
    const int* __restrict__ gather,
    int m0, int ne, char* dsm,
    float (&acc)[4][4][4], int wm, int wn)
{
    const int tid = threadIdx.x;
    const int lane = tid & 31;
    uint32_t sbase = smem_u32(dsm);

    size_t aoff[2]; uint32_t adst[2];
    #pragma unroll
    for (int t = 0; t < 2; t++) {
        int c = tid + t * 256;
        int row = c >> 2, sub = c & 3;
        int m = m0 + row;
        int ridx = gather ? ((m < ne) ? gather[m] : 0) : m;
        aoff[t] = (size_t)ridx * KTOT + sub * 8;
        adst[t] = (uint32_t)(row * (A_LD32 * 2) + sub * 16);
    }
    size_t boff[2]; uint32_t bdst[2];
    #pragma unroll
    for (int t = 0; t < 2; t++) {
        int c = tid + t * 256;
        int row = c >> 4, sub = c & 15;
        boff[t] = (size_t)row * NS + sub * 8;
        bdst[t] = (uint32_t)(A_BYTES32 + row * (B_LD32 * 2) + sub * 16);
    }

    auto issue = [&](int ks) {
        uint32_t sb = sbase + (ks & 1) * STAGE32;
        int k0 = ks * KS32;
        cp16(sb + adst[0], Abase + aoff[0] + k0);
        cp16(sb + adst[1], Abase + aoff[1] + k0);
        const __half* bk = Bn0 + (size_t)k0 * NS;
        cp16(sb + bdst[0], bk + boff[0]);
        cp16(sb + bdst[1], bk + boff[1]);
        cp_commit();
    };

    const uint32_t a_lane = (uint32_t)((lane & 15) * (A_LD32 * 2) + (lane >> 4) * 16);
    const uint32_t b_lane = (uint32_t)((lane & 15) * (B_LD32 * 2) + (lane >> 4) * 16);

    constexpr int NK = KTOT / KS32;
    issue(0);

    for (int ks = 0; ks < NK; ks++) {
        cp_waitn<0>();
        __syncthreads();
        if (ks + 1 < NK) issue(ks + 1);

        uint32_t As = sbase + (ks & 1) * STAGE32;
        uint32_t Bs = As + A_BYTES32;

        #pragma unroll
        for (int kk = 0; kk < 2; kk++) {
            uint32_t b[8];
            uint32_t bb = Bs + kk * 16 * (B_LD32 * 2) + wn * 64 + b_lane;
            ldsm4t(b[0], b[1], b[2], b[3], bb);
            ldsm4t(b[4], b[5], b[6], b[7], bb + 32);
            #pragma unroll
            for (int i = 0; i < 4; i++) {
                uint32_t a[4];
                ldsm4(a[0], a[1], a[2], a[3],
                      As + (uint32_t)((wm * 64 + i * 16) * (A_LD32 * 2)) + kk * 32 + a_lane);
                #pragma unroll
                for (int jn = 0; jn < 4; jn++)
                    mma16816(acc[i][jn], a, &b[jn * 2]);
            }
        }
    }
}

// ---------------- epilogues ----------------
__device__ __forceinline__ void epi1(int e, int ne, int m0, int n0, int wm, int wn,
                                     int lane, float (&acc)[4][4][4],
                                     const float* __restrict__ bin) {
    int gid = lane >> 2, t4 = lane & 3;
    #pragma unroll
    for (int i = 0; i < 4; i++) {
        int r0 = m0 + wm * 64 + i * 16 + gid;
        int r1 = r0 + 8;
        #pragma unroll
        for (int jn = 0; jn < 4; jn++) {
            int col = n0 + wn * 32 + jn * 8 + t4 * 2;
            float b0 = bin[e * HDIM + col], b1 = bin[e * HDIM + col + 1];
            if (r0 < ne) {
                float v0 = acc[i][jn][0] + b0;
                float v1 = acc[i][jn][1] + b1;
                v0 = 0.5f * v0 * (1.0f + erff(v0 * 0.70710678118654752f));
                v1 = 0.5f * v1 * (1.0f + erff(v1 * 0.70710678118654752f));
                *(__half2*)(g_h16 + ((size_t)e * CAPE + r0) * HDIM + col) =
                    __halves2half2(__float2half_rn(v0), __float2half_rn(v1));
            }
            if (r1 < ne) {
                float v2 = acc[i][jn][2] + b0;
                float v3 = acc[i][jn][3] + b1;
                v2 = 0.5f * v2 * (1.0f + erff(v2 * 0.70710678118654752f));
                v3 = 0.5f * v3 * (1.0f + erff(v3 * 0.70710678118654752f));
                *(__half2*)(g_h16 + ((size_t)e * CAPE + r1) * HDIM + col) =
                    __halves2half2(__float2half_rn(v2), __float2half_rn(v3));
            }
        }
    }
}

__device__ __forceinline__ void epi2(int e, int ne, int m0, int n0, int wm, int wn,
                                     int lane, float (&acc)[4][4][4],
                                     const float* __restrict__ bout,
                                     float* __restrict__ out) {
    int gid = lane >> 2, t4 = lane & 3;
    #pragma unroll
    for (int i = 0; i < 4; i++) {
        int r0 = m0 + wm * 64 + i * 16 + gid;
        int r1 = r0 + 8;
        int tok0 = -1, tok1 = -1; float wt0 = 0.0f, wt1 = 0.0f;
        if (r0 < ne) { tok0 = g_tokens[e * CAPE + r0]; wt0 = g_wts[e * CAPE + r0]; }
        if (r1 < ne) { tok1 = g_tokens[e * CAPE + r1]; wt1 = g_wts[e * CAPE + r1]; }
        #pragma unroll
        for (int jn = 0; jn < 4; jn++) {
            int col = n0 + wn * 32 + jn * 8 + t4 * 2;
            float b0 = bout[e * DDIM + col], b1 = bout[e * DDIM + col + 1];
            if (tok0 >= 0) {
                atomicAdd(out + (size_t)tok0 * DDIM + col,     wt0 * (acc[i][jn][0] + b0));
                atomicAdd(out + (size_t)tok0 * DDIM + col + 1, wt0 * (acc[i][jn][1] + b1));
            }
            if (tok1 >= 0) {
                atomicAdd(out + (size_t)tok1 * DDIM + col,     wt1 * (acc[i][jn][2] + b0));
                atomicAdd(out + (size_t)tok1 * DDIM + col + 1, wt1 * (acc[i][jn][3] + b1));
            }
        }
    }
}

// ---------------- gemm kernels ----------------
__global__ __launch_bounds__(256, 2) void k_gemm1_dyn(const float* __restrict__ bin) {
    extern __shared__ __align__(32) char dsm[];
    int e  = blockIdx.z;
    int ne = g_counts[e];
    int m0 = blockIdx.y * 128;
    if (m0 >= ne) return;
    int n0 = blockIdx.x * 128;
    int tid = threadIdx.x, wid = tid >> 5, lane = tid & 31;
    int wm = wid >> 2, wn = wid & 3;

    float acc[4][4][4];
    #pragma unroll
    for (int i = 0; i < 4; i++)
        #pragma unroll
        for (int j = 0; j < 4; j++)
            #pragma unroll
            for (int q = 0; q < 4; q++) acc[i][j][q] = 0.0f;

    mainloop64<DDIM, HDIM>(g_x16, g_w1 + (size_t)e * DDIM * HDIM + n0,
                           g_tokens + e * CAPE, m0, ne, dsm, acc, wm, wn);
    epi1(e, ne, m0, n0, wm, wn, lane, acc, bin);
}

__global__ __launch_bounds__(256, 2) void k_gemm2_dyn(const float* __restrict__ bout,
                                                      float* __restrict__ out) {
    extern __shared__ __align__(32) char dsm[];
    int e  = blockIdx.z;
    int ne = g_counts[e];
    int m0 = blockIdx.y * 128;
    if (m0 >= ne) return;
    int n0 = blockIdx.x * 128;
    int tid = threadIdx.x, wid = tid >> 5, lane = tid & 31;
    int wm = wid >> 2, wn = wid & 3;

    float acc[4][4][4];
    #pragma unroll
    for (int i = 0; i < 4; i++)
        #pragma unroll
        for (int j = 0; j < 4; j++)
            #pragma unroll
            for (int q = 0; q < 4; q++) acc[i][j][q] = 0.0f;

    mainloop64<HDIM, DDIM>(g_h16 + (size_t)e * CAPE * HDIM,
                           g_w2 + (size_t)e * HDIM * DDIM + n0,
                           nullptr, m0, ne, dsm, acc, wm, wn);
    epi2(e, ne, m0, n0, wm, wn, lane, acc, bout, out);
}

__global__ __launch_bounds__(256) void k_gemm1_sta(const float* __restrict__ bin) {
    __shared__ __align__(32) char dsm[SMEM_STA];
    int e  = blockIdx.z;
    int ne = g_counts[e];
    int m0 = blockIdx.y * 128;
    if (m0 >= ne) return;
    int n0 = blockIdx.x * 128;
    int tid = threadIdx.x, wid = tid >> 5, lane = tid & 31;
    int wm = wid >> 2, wn = wid & 3;

    float acc[4][4][4];
    #pragma unroll
    for (int i = 0; i < 4; i++)
        #pragma unroll
        for (int j = 0; j < 4; j++)
            #pragma unroll
            for (int q = 0; q < 4; q++) acc[i][j][q] = 0.0f;

    mainloop32<DDIM, HDIM>(g_x16, g_w1 + (size_t)e * DDIM * HDIM + n0,
                           g_tokens + e * CAPE, m0, ne, dsm, acc, wm, wn);
    epi1(e, ne, m0, n0, wm, wn, lane, acc, bin);
}

__global__ __launch_bounds__(256) void k_gemm2_sta(const float* __restrict__ bout,
                                                   float* __restrict__ out) {
    __shared__ __align__(32) char dsm[SMEM_STA];
    int e  = blockIdx.z;
    int ne = g_counts[e];
    int m0 = blockIdx.y * 128;
    if (m0 >= ne) return;
    int n0 = blockIdx.x * 128;
    int tid = threadIdx.x, wid = tid >> 5, lane = tid & 31;
    int wm = wid >> 2, wn = wid & 3;

    float acc[4][4][4];
    #pragma unroll
    for (int i = 0; i < 4; i++)
        #pragma unroll
        for (int j = 0; j < 4; j++)
            #pragma unroll
            for (int q = 0; q < 4; q++) acc[i][j][q] = 0.0f;

    mainloop32<HDIM, DDIM>(g_h16 + (size_t)e * CAPE * HDIM,
                           g_w2 + (size_t)e * HDIM * DDIM + n0,
                           nullptr, m0, ne, dsm, acc, wm, wn);
    epi2(e, ne, m0, n0, wm, wn, lane, acc, bout, out);
}

// ---------------- launch ----------------
extern "C" void kernel_launch(void* const* d_in, const int* in_sizes, int n_in,
                              void* d_out, int out_size) {
    const float* x    = (const float*)d_in[0];
    const float* rw   = (const float*)d_in[1];
    const float* Win  = (const float*)d_in[2];
    const float* bin  = (const float*)d_in[3];
    const float* Wout = (const float*)d_in[4];
    const float* bout = (const float*)d_in[5];
    float* out = (float*)d_out;

    cudaError_t a1 = cudaFuncSetAttribute(
        k_gemm1_dyn, cudaFuncAttributeMaxDynamicSharedMemorySize, SMEM_DYN);
    cudaError_t a2 = cudaFuncSetAttribute(
        k_gemm2_dyn, cudaFuncAttributeMaxDynamicSharedMemorySize, SMEM_DYN);
    bool use_dyn = (a1 == cudaSuccess) && (a2 == cudaSuccess);

    dim3 g1(HDIM / 128, CAPE / 128, NEXP);
    dim3 g2(DDIM / 128, CAPE / 128, NEXP);

    k_cvt_x<<<512, 256>>>(x);                    // also zeroes routing state
    k_router<<<NTOK / 8, 256>>>(x, rw);
    k_cvt_w1<<<2048, 256>>>(Win);
    if (use_dyn) k_gemm1_dyn<<<g1, 256, SMEM_DYN>>>(bin);
    else         k_gemm1_sta<<<g1, 256>>>(bin);
    k_cvt_w2<<<2048, 256>>>(Wout);
    k_zero_out<<<512, 256>>>(out);
    if (use_dyn) k_gemm2_dyn<<<g2, 256, SMEM_DYN>>>(bout, out);
    else         k_gemm2_sta<<<g2, 256>>>(bout, out);
    k_aux<<<1, 32>>>(out, out_size);
}